// round 10
// baseline (speedup 1.0000x reference)
#include <cuda_runtime.h>
#include <cuda_bf16.h>

// Problem constants
#define BB 8
#define NN 2048
#define CIN 64
#define CC 128
#define KK 16
#define FF 512
#define NP (BB*NN)          // 16384 points
#define NR (NP*KK)          // 262144 t-rows

// ---------------- scratch ----------------------------------------------------
__device__ float g_h   [NP*CC];
__device__ float g_hn  [NP*CC];
__device__ float g_qa  [NP*CC];
__device__ float g_ka  [NP*CC];
__device__ float g_v   [NP*CC];
__device__ float g_hnew[NP*CC];
__device__ float g_h2  [NP*CC];
__device__ float g_t512[NP*FF];
__device__ int   g_idx [NP*KK];

__device__ float    g_WinT[CIN*CC];
__device__ float    g_WvT [CC*CC];
__device__ float    g_WaqT[CC*CC];
__device__ float    g_WakT[CC*CC];
__device__ float    g_cd  [CC];              // Wa@bd2 + ba
// B operand, repacked for LDG.128:
// g_W2p[col*128 + (k&3)*32 + (k>>2)] = tf32(W[k][col]), col 0..127 = Wd2T, 128..255 = (WaWd2)T
__device__ unsigned g_W2p [256*CC];
__device__ float    g_Wf1T[CC*FF];
__device__ float    g_Wf2T[FF*CC];

// ---------------- helpers ----------------------------------------------------
__device__ __forceinline__ unsigned long long pack2(float x){
    unsigned long long r; asm("mov.b64 %0, {%1, %1};" : "=l"(r) : "f"(x)); return r;
}
__device__ __forceinline__ void fma2(unsigned long long &a, unsigned long long b, unsigned long long c){
    asm("fma.rn.f32x2 %0, %1, %2, %0;" : "+l"(a) : "l"(b), "l"(c));
}
__device__ __forceinline__ float2 unpack2(unsigned long long v){
    float2 f; asm("mov.b64 {%0, %1}, %2;" : "=f"(f.x), "=f"(f.y) : "l"(v)); return f;
}
__device__ __forceinline__ unsigned f2tf32(float f){
    unsigned u; asm("cvt.rna.tf32.f32 %0, %1;" : "=r"(u) : "f"(f)); return u;
}
__device__ __forceinline__ void mma_tf32(float* d, const unsigned* a, const unsigned* b){
    asm("mma.sync.aligned.m16n8k8.row.col.f32.tf32.tf32.f32 "
        "{%0,%1,%2,%3},{%4,%5,%6,%7},{%8,%9},{%0,%1,%2,%3};"
        : "+f"(d[0]),"+f"(d[1]),"+f"(d[2]),"+f"(d[3])
        : "r"(a[0]),"r"(a[1]),"r"(a[2]),"r"(a[3]), "r"(b[0]),"r"(b[1]));
}

// ---------------- prep kernels -----------------------------------------------
__global__ void k_prep_tr(const float* __restrict__ Win, const float* __restrict__ Wd2,
                          const float* __restrict__ Wv,  const float* __restrict__ Wf1,
                          const float* __restrict__ Wf2){
    int i = blockIdx.x*blockDim.x + threadIdx.x;   // 0..65535
    if (i < CIN*CC){ int c=i>>7, o=i&127; g_WinT[i] = Win[o*CIN+c]; }
    if (i < CC*CC){  int c=i>>7, o=i&127;           // c = k index, o = col
        float wd2 = Wd2[o*CC+c];
        g_W2p[o*128 + (c&3)*32 + (c>>2)] = f2tf32(wd2);
        g_WvT[i] = Wv[o*CC+c]; }
    if (i < CC*FF){  int c=i>>9, r=i&511; g_Wf1T[i] = Wf1[r*CC+c]; }
    if (i < FF*CC){  int r=i>>7, o=i&127; g_Wf2T[i] = Wf2[o*FF+r]; }
}

__global__ void k_prep_combo(const float* __restrict__ Wa, const float* __restrict__ Wq,
                             const float* __restrict__ Wk, const float* __restrict__ Wd2){
    int o = blockIdx.x;          // 0..127 (output row of combo = B column)
    int c = threadIdx.x;         // 0..127 (k index)
    const float* src = (blockIdx.y==0)?Wq : (blockIdx.y==1)?Wk : Wd2;
    float acc = 0.f;
    #pragma unroll 4
    for (int m=0; m<CC; m++) acc = fmaf(Wa[o*CC+m], src[m*CC+c], acc);
    if (blockIdx.y==0)      g_WaqT[c*CC+o] = acc;
    else if (blockIdx.y==1) g_WakT[c*CC+o] = acc;
    else                    g_W2p[(128+o)*128 + (c&3)*32 + (c>>2)] = f2tf32(acc);
}

__global__ void k_prep_cd(const float* __restrict__ Wa, const float* __restrict__ bd2,
                          const float* __restrict__ ba){
    int o = threadIdx.x;
    float acc = ba[o];
    #pragma unroll 4
    for (int c=0;c<CC;c++) acc = fmaf(Wa[o*CC+c], bd2[c], acc);
    g_cd[o] = acc;
}

// ---------------- in_proj ----------------------------------------------------
__global__ void __launch_bounds__(128) k_inproj(const float* __restrict__ x,
                                                const float* __restrict__ binv){
    __shared__ __align__(16) float xs[CIN][16];
    int blk = blockIdx.x;
    int b   = blk >> 7;
    int n0  = (blk & 127) << 4;
    int pt0 = b*NN + n0;
    int tid = threadIdx.x;
    const float* xb = x + (size_t)b*CIN*NN;
    for (int f=tid; f<CIN*16; f+=128){ int c=f>>4, m=f&15; xs[c][m] = xb[c*NN + n0 + m]; }
    __syncthreads();
    unsigned long long acc[8];
    #pragma unroll
    for (int i=0;i<8;i++) acc[i]=0ull;
    #pragma unroll 2
    for (int c=0;c<CIN;c++){
        unsigned long long w2 = pack2(g_WinT[c*CC + tid]);
        const ulonglong2* xp = (const ulonglong2*)xs[c];
        ulonglong2 v0=xp[0], v1=xp[1], v2=xp[2], v3=xp[3];
        fma2(acc[0],w2,v0.x); fma2(acc[1],w2,v0.y);
        fma2(acc[2],w2,v1.x); fma2(acc[3],w2,v1.y);
        fma2(acc[4],w2,v2.x); fma2(acc[5],w2,v2.y);
        fma2(acc[6],w2,v3.x); fma2(acc[7],w2,v3.y);
    }
    float bo = binv[tid];
    #pragma unroll
    for (int i=0;i<8;i++){
        float2 f = unpack2(acc[i]);
        g_h[(size_t)(pt0+2*i)*CC   + tid] = f.x + bo;
        g_h[(size_t)(pt0+2*i+1)*CC + tid] = f.y + bo;
    }
}

// ---------------- LayerNorm ---------------------------------------------------
__global__ void __launch_bounds__(128) k_ln(const float* __restrict__ in, float* __restrict__ out,
                                            const float* __restrict__ g, const float* __restrict__ bbv){
    __shared__ float ws[4];
    int pt = blockIdx.x, t = threadIdx.x;
    float v = in[(size_t)pt*CC + t];
    float s = v;
    #pragma unroll
    for (int o=16;o;o>>=1) s += __shfl_xor_sync(0xffffffffu, s, o);
    if ((t&31)==0) ws[t>>5] = s;
    __syncthreads();
    float mu = (ws[0]+ws[1]+ws[2]+ws[3]) * (1.f/CC);
    float dv = v - mu;
    __syncthreads();
    float q = dv*dv;
    #pragma unroll
    for (int o=16;o;o>>=1) q += __shfl_xor_sync(0xffffffffu, q, o);
    if ((t&31)==0) ws[t>>5] = q;
    __syncthreads();
    float var = (ws[0]+ws[1]+ws[2]+ws[3]) * (1.f/CC);
    out[(size_t)pt*CC + t] = dv * rsqrtf(var + 1e-5f) * g[t] + bbv[t];
}

// ---------------- KNN: warp-per-query, register top-16 ------------------------
__global__ void __launch_bounds__(512) k_knn(const float* __restrict__ p, int* __restrict__ idx_out){
    __shared__ float px[NN], py[NN], pz[NN], sw[NN];
    int blk = blockIdx.x;
    int b   = blk >> 7;
    int n0  = (blk & 127) << 4;
    int tid = threadIdx.x, lane = tid & 31, w = tid >> 5;
    const float* pb = p + (size_t)b*3*NN;
    for (int i=tid;i<NN;i+=512){
        float x=pb[i], y=pb[NN+i], z=pb[2*NN+i];
        px[i]=x; py[i]=y; pz[i]=z;
        sw[i]=x*x + y*y + z*z;
    }
    __syncthreads();
    int n = n0 + w;
    float qx=px[n], qy=py[n], qz=pz[n];
    float xxq = sw[n];
    float qx2 = 2.f*qx, qy2 = 2.f*qy, qz2 = 2.f*qz;
    unsigned long long t[16];
    #pragma unroll
    for (int a=0;a<16;a++) t[a]=0ull;
    #pragma unroll 4
    for (int i=lane;i<NN;i+=32){
        float s = fmaf(qx2, px[i], fmaf(qy2, py[i], fmaf(qz2, pz[i], -xxq - sw[i])));
        unsigned u = __float_as_uint(s);
        u ^= (u & 0x80000000u) ? 0xFFFFFFFFu : 0x80000000u;
        unsigned long long key = ((unsigned long long)u << 32) | (unsigned)(~i);
        if (i == n) key = 0ull;
        if (key > t[15]){
            unsigned long long cur = key;
            #pragma unroll
            for (int a=0;a<16;a++){
                unsigned long long old = t[a];
                bool gt = cur > old;
                t[a] = gt ? cur : old;
                cur  = gt ? old : cur;
            }
        }
    }
    unsigned long long head = t[0];
    unsigned myres = 0;
    #pragma unroll
    for (int r=0;r<16;r++){
        unsigned long long m = head;
        #pragma unroll
        for (int o=16;o;o>>=1){
            unsigned long long v = __shfl_xor_sync(0xffffffffu, m, o);
            if (v > m) m = v;
        }
        if (lane == r) myres = ~(unsigned)m;
        if (head == m){
            #pragma unroll
            for (int a=0;a<15;a++) t[a]=t[a+1];
            t[15]=0ull;
            head = t[0];
        }
    }
    if (lane < KK) idx_out[((size_t)b*NN + n)*KK + lane] = (int)myres;
}

// ---------------- projections -------------------------------------------------
__global__ void __launch_bounds__(128) k_proj(){
    __shared__ __align__(16) float hs[CC][16];
    int pt0 = blockIdx.x * 16;
    int tid = threadIdx.x;
    for (int f=tid; f<CC*16; f+=128) hs[f&127][f>>7] = g_hn[(size_t)pt0*CC + f];
    __syncthreads();
    unsigned long long aq[8], ak[8], av[8];
    #pragma unroll
    for (int i=0;i<8;i++){ aq[i]=0ull; ak[i]=0ull; av[i]=0ull; }
    for (int c=0;c<CC;c++){
        unsigned long long wq = pack2(g_WaqT[c*CC+tid]);
        unsigned long long wk = pack2(g_WakT[c*CC+tid]);
        unsigned long long wv = pack2(g_WvT [c*CC+tid]);
        const ulonglong2* hp = (const ulonglong2*)hs[c];
        ulonglong2 v0=hp[0], v1=hp[1], v2=hp[2], v3=hp[3];
        fma2(aq[0],wq,v0.x); fma2(aq[1],wq,v0.y); fma2(aq[2],wq,v1.x); fma2(aq[3],wq,v1.y);
        fma2(aq[4],wq,v2.x); fma2(aq[5],wq,v2.y); fma2(aq[6],wq,v3.x); fma2(aq[7],wq,v3.y);
        fma2(ak[0],wk,v0.x); fma2(ak[1],wk,v0.y); fma2(ak[2],wk,v1.x); fma2(ak[3],wk,v1.y);
        fma2(ak[4],wk,v2.x); fma2(ak[5],wk,v2.y); fma2(ak[6],wk,v3.x); fma2(ak[7],wk,v3.y);
        fma2(av[0],wv,v0.x); fma2(av[1],wv,v0.y); fma2(av[2],wv,v1.x); fma2(av[3],wv,v1.y);
        fma2(av[4],wv,v2.x); fma2(av[5],wv,v2.y); fma2(av[6],wv,v3.x); fma2(av[7],wv,v3.y);
    }
    #pragma unroll
    for (int i=0;i<8;i++){
        float2 fq = unpack2(aq[i]), fk = unpack2(ak[i]), fv = unpack2(av[i]);
        size_t b0 = (size_t)(pt0+2*i)*CC + tid;
        size_t b1 = (size_t)(pt0+2*i+1)*CC + tid;
        g_qa[b0]=fq.x; g_qa[b1]=fq.y;
        g_ka[b0]=fk.x; g_ka[b1]=fk.y;
        g_v [b0]=fv.x; g_v [b1]=fv.y;
    }
}

// ---------------- fused attention GEMM + softmax + combine --------------------
// Block: 4 points = 64 t-rows x 256 cols, 256 threads (2m x 4n warps, 32x64 tiles).
// Smaller block than before: 65KB dynamic smem -> 2-3 CTAs/SM so independent
// CTAs overlap phases (mainloop hides epilogue gather latency of the other CTA).
#define DS_STRIDE 260
#define AROWS 64
__global__ void __launch_bounds__(256) k_attn_fused(const float* __restrict__ p,
                                                    const float* __restrict__ Wd1,
                                                    const float* __restrict__ bd1,
                                                    const float* __restrict__ bd2v){
    extern __shared__ __align__(16) unsigned smem_u[];   // 64*260*4 = 66560 B
    unsigned* As = smem_u;                                // [64][132] during mainloop
    float*    Ds = (float*)smem_u;                        // [64][260] during epilogue
    __shared__ float wd1s[CC][3];
    __shared__ float bd1s[CC];
    __shared__ float rel3[AROWS][3];
    __shared__ int   idxs[AROWS];

    int tid = threadIdx.x;
    int pt0 = blockIdx.x * 4;

    if (tid < CC){
        wd1s[tid][0]=Wd1[tid*3]; wd1s[tid][1]=Wd1[tid*3+1]; wd1s[tid][2]=Wd1[tid*3+2];
        bd1s[tid]=bd1[tid];
    }
    if (tid < AROWS){
        int row = tid;
        int pt  = pt0 + (row>>4);
        int j   = row & 15;
        int b   = pt >> 11, n = pt & (NN-1);
        int jn  = g_idx[(size_t)pt*KK + j];
        idxs[row] = jn;
        const float* pb = p + (size_t)b*3*NN;
        rel3[row][0] = pb[n]      - pb[jn];
        rel3[row][1] = pb[NN+n]   - pb[NN+jn];
        rel3[row][2] = pb[2*NN+n] - pb[2*NN+jn];
    }
    __syncthreads();
    for (int e=tid; e<AROWS*128; e+=256){
        int row = e >> 7, c = e & 127;
        float t = fmaf(wd1s[c][0], rel3[row][0],
                  fmaf(wd1s[c][1], rel3[row][1],
                  fmaf(wd1s[c][2], rel3[row][2], bd1s[c])));
        As[row*132 + c] = f2tf32(fmaxf(t, 0.f));
    }
    __syncthreads();

    int wid = tid >> 5, lane = tid & 31;
    int wm = wid & 1, wn = wid >> 1;          // 2 x 4 warp grid
    int g  = lane >> 2, tg = lane & 3;
    float acc[2][8][4];
    #pragma unroll
    for (int mi=0;mi<2;mi++)
        #pragma unroll
        for (int ni=0;ni<8;ni++)
            #pragma unroll
            for (int q=0;q<4;q++) acc[mi][ni][q]=0.f;

    int cg = wn*64 + g;                        // column (+ni*8) this thread reads B for
    const uint4* Bp = (const uint4*)(g_W2p + (size_t)cg*128 + tg*32);
    #pragma unroll
    for (int ks2=0; ks2<8; ks2++){
        uint4 bfr[8];
        #pragma unroll
        for (int ni=0;ni<8;ni++) bfr[ni] = Bp[ni*8*32 + ks2];   // (ni*8 cols)*128/4 uint4
        #pragma unroll
        for (int ksi=0; ksi<2; ksi++){
            int k = (ks2*2 + ksi)*8;
            unsigned afr[2][4];
            #pragma unroll
            for (int mi=0;mi<2;mi++){
                int rb = wm*32 + mi*16;
                afr[mi][0] = As[(rb+g   )*132 + k + tg  ];
                afr[mi][1] = As[(rb+g+8 )*132 + k + tg  ];
                afr[mi][2] = As[(rb+g   )*132 + k + tg+4];
                afr[mi][3] = As[(rb+g+8 )*132 + k + tg+4];
            }
            #pragma unroll
            for (int ni=0;ni<8;ni++){
                unsigned bb[2];
                bb[0] = ksi ? bfr[ni].z : bfr[ni].x;
                bb[1] = ksi ? bfr[ni].w : bfr[ni].y;
                #pragma unroll
                for (int mi=0;mi<2;mi++) mma_tf32(acc[mi][ni], afr[mi], bb);
            }
        }
    }
    __syncthreads();                 // everyone done reading As
    // write accumulators to Ds
    #pragma unroll
    for (int mi=0;mi<2;mi++){
        int r0 = wm*32 + mi*16 + g;
        #pragma unroll
        for (int ni=0;ni<8;ni++){
            int c0 = wn*64 + ni*8 + 2*tg;
            Ds[r0*DS_STRIDE + c0]     = acc[mi][ni][0];
            Ds[r0*DS_STRIDE + c0 + 1] = acc[mi][ni][1];
            Ds[(r0+8)*DS_STRIDE + c0]     = acc[mi][ni][2];
            Ds[(r0+8)*DS_STRIDE + c0 + 1] = acc[mi][ni][3];
        }
    }
    __syncthreads();
    // finish: softmax over neighbors + combine (2 items per thread)
    #pragma unroll
    for (int it=0; it<2; it++){
        int item = it*256 + tid;
        int c    = item & 127;
        int ptl  = item >> 7;        // 0..3
        int pt   = pt0 + ptl;
        int b    = pt >> 11;
        float bd2o = bd2v[c];
        float base = g_qa[(size_t)pt*CC + c] + g_cd[c];
        float d[KK], l[KK];
        float mx = -3.4e38f;
        #pragma unroll
        for (int j=0;j<KK;j++){
            int row = ptl*16 + j;
            d[j] = Ds[row*DS_STRIDE + c] + bd2o;
            l[j] = Ds[row*DS_STRIDE + 128 + c] + base
                 - g_ka[((size_t)b*NN + idxs[row])*CC + c];
            mx = fmaxf(mx, l[j]);
        }
        float s = 0.f;
        #pragma unroll
        for (int j=0;j<KK;j++){ l[j] = __expf(l[j]-mx); s += l[j]; }
        float y = 0.f;
        #pragma unroll
        for (int j=0;j<KK;j++){
            int row = ptl*16 + j;
            float vj = g_v[((size_t)b*NN + idxs[row])*CC + c];
            y = fmaf(l[j], vj + d[j], y);
        }
        y /= s;
        g_hnew[(size_t)pt*CC + c] = g_h[(size_t)pt*CC + c] + y;
    }
}

// ---------------- FFN stage 1 -------------------------------------------------
__global__ void __launch_bounds__(256) k_ffn1(const float* __restrict__ bf1){
    __shared__ __align__(16) float hs[CC][16];
    int pt0 = blockIdx.x * 16;
    int tid = threadIdx.x;
    for (int f=tid; f<CC*16; f+=256) hs[f&127][f>>7] = g_h2[(size_t)pt0*CC + f];
    __syncthreads();
    unsigned long long a0[8], a1[8];
    #pragma unroll
    for (int i=0;i<8;i++){ a0[i]=0ull; a1[i]=0ull; }
    for (int c=0;c<CC;c++){
        unsigned long long w0 = pack2(g_Wf1T[c*FF + tid]);
        unsigned long long w1 = pack2(g_Wf1T[c*FF + tid + 256]);
        const ulonglong2* hp = (const ulonglong2*)hs[c];
        ulonglong2 v0=hp[0], v1=hp[1], v2=hp[2], v3=hp[3];
        fma2(a0[0],w0,v0.x); fma2(a0[1],w0,v0.y); fma2(a0[2],w0,v1.x); fma2(a0[3],w0,v1.y);
        fma2(a0[4],w0,v2.x); fma2(a0[5],w0,v2.y); fma2(a0[6],w0,v3.x); fma2(a0[7],w0,v3.y);
        fma2(a1[0],w1,v0.x); fma2(a1[1],w1,v0.y); fma2(a1[2],w1,v1.x); fma2(a1[3],w1,v1.y);
        fma2(a1[4],w1,v2.x); fma2(a1[5],w1,v2.y); fma2(a1[6],w1,v3.x); fma2(a1[7],w1,v3.y);
    }
    float b0 = bf1[tid], b1v = bf1[tid+256];
    #pragma unroll
    for (int i=0;i<8;i++){
        float2 f0 = unpack2(a0[i]), f1 = unpack2(a1[i]);
        g_t512[(size_t)(pt0+2*i)*FF   + tid]       = fmaxf(f0.x+b0, 0.f);
        g_t512[(size_t)(pt0+2*i+1)*FF + tid]       = fmaxf(f0.y+b0, 0.f);
        g_t512[(size_t)(pt0+2*i)*FF   + tid + 256] = fmaxf(f1.x+b1v, 0.f);
        g_t512[(size_t)(pt0+2*i+1)*FF + tid + 256] = fmaxf(f1.y+b1v, 0.f);
    }
}

// ---------------- FFN stage 2 + residual + transpose --------------------------
__global__ void __launch_bounds__(128) k_ffn2(const float* __restrict__ bf2, float* __restrict__ out){
    __shared__ __align__(16) float ts[FF][16];
    int pt0 = blockIdx.x * 16;
    int b   = pt0 >> 11;
    int n0  = pt0 & (NN-1);
    int tid = threadIdx.x;
    for (int f=tid; f<FF*16; f+=128) ts[f&511][f>>9] = g_t512[(size_t)pt0*FF + f];
    __syncthreads();
    unsigned long long acc[8];
    #pragma unroll
    for (int i=0;i<8;i++) acc[i]=0ull;
    #pragma unroll 2
    for (int r=0;r<FF;r++){
        unsigned long long w2 = pack2(g_Wf2T[r*CC + tid]);
        const ulonglong2* tp = (const ulonglong2*)ts[r];
        ulonglong2 v0=tp[0], v1=tp[1], v2=tp[2], v3=tp[3];
        fma2(acc[0],w2,v0.x); fma2(acc[1],w2,v0.y);
        fma2(acc[2],w2,v1.x); fma2(acc[3],w2,v1.y);
        fma2(acc[4],w2,v2.x); fma2(acc[5],w2,v2.y);
        fma2(acc[6],w2,v3.x); fma2(acc[7],w2,v3.y);
    }
    float bo = bf2[tid];
    float res[16];
    #pragma unroll
    for (int i=0;i<8;i++){
        float2 f = unpack2(acc[i]);
        res[2*i]   = g_hnew[(size_t)(pt0+2*i)*CC   + tid] + f.x + bo;
        res[2*i+1] = g_hnew[(size_t)(pt0+2*i+1)*CC + tid] + f.y + bo;
    }
    __syncthreads();
    float* os = &ts[0][0];
    #pragma unroll
    for (int m=0;m<16;m++) os[m*CC + tid] = res[m];
    __syncthreads();
    for (int f=tid; f<16*CC; f+=128){
        int o = f >> 4, m = f & 15;
        out[(size_t)b*CC*NN + (size_t)o*NN + n0 + m] = os[m*CC + o];
    }
}

// ---------------- launch ------------------------------------------------------
extern "C" void kernel_launch(void* const* d_in, const int* in_sizes, int n_in,
                              void* d_out, int out_size){
    const float* x    = (const float*)d_in[0];
    const float* p    = (const float*)d_in[1];
    const float* Win  = (const float*)d_in[2];
    const float* bin_ = (const float*)d_in[3];
    const float* Wq   = (const float*)d_in[4];
    const float* Wk   = (const float*)d_in[5];
    const float* Wv   = (const float*)d_in[6];
    const float* Wd1  = (const float*)d_in[7];
    const float* bd1  = (const float*)d_in[8];
    const float* Wd2  = (const float*)d_in[9];
    const float* bd2  = (const float*)d_in[10];
    const float* Wa   = (const float*)d_in[11];
    const float* ba   = (const float*)d_in[12];
    const float* g1   = (const float*)d_in[13];
    const float* b1   = (const float*)d_in[14];
    const float* g2   = (const float*)d_in[15];
    const float* b2   = (const float*)d_in[16];
    const float* Wf1  = (const float*)d_in[17];
    const float* bf1  = (const float*)d_in[18];
    const float* Wf2  = (const float*)d_in[19];
    const float* bf2  = (const float*)d_in[20];
    float* out = (float*)d_out;

    const int FUSED_SMEM = AROWS*DS_STRIDE*4;   // 66560
    cudaFuncSetAttribute(k_attn_fused, cudaFuncAttributeMaxDynamicSharedMemorySize, FUSED_SMEM);

    k_prep_tr<<<256, 256>>>(Win, Wd2, Wv, Wf1, Wf2);
    k_prep_combo<<<dim3(128,3), 128>>>(Wa, Wq, Wk, Wd2);
    k_prep_cd<<<1, 128>>>(Wa, bd2, ba);

    k_inproj<<<NP/16, 128>>>(x, bin_);
    {
        float *hp, *hnp;
        cudaGetSymbolAddress((void**)&hp,  g_h);
        cudaGetSymbolAddress((void**)&hnp, g_hn);
        k_ln<<<NP, 128>>>(hp, hnp, g1, b1);
    }
    {
        int* ip; cudaGetSymbolAddress((void**)&ip, g_idx);
        k_knn<<<NP/16, 512>>>(p, ip);
    }
    k_proj<<<NP/16, 128>>>();
    k_attn_fused<<<NP/4, 256, FUSED_SMEM>>>(p, Wd1, bd1, bd2);
    {
        float *hp, *h2p;
        cudaGetSymbolAddress((void**)&hp,  g_hnew);
        cudaGetSymbolAddress((void**)&h2p, g_h2);
        k_ln<<<NP, 128>>>(hp, h2p, g2, b2);
    }
    k_ffn1<<<NP/16, 256>>>(bf1);
    k_ffn2<<<NP/16, 128>>>(bf2, out);
}

// round 12
// speedup vs baseline: 1.0347x; 1.0347x over previous
#include <cuda_runtime.h>
#include <cuda_bf16.h>

// Problem constants
#define BB 8
#define NN 2048
#define CIN 64
#define CC 128
#define KK 16
#define FF 512
#define NP (BB*NN)          // 16384 points
#define NR (NP*KK)          // 262144 t-rows

// ---------------- scratch ----------------------------------------------------
__device__ float g_h   [NP*CC];
__device__ float g_hn  [NP*CC];
__device__ float g_qa  [NP*CC];
__device__ float g_ka  [NP*CC];
__device__ float g_v   [NP*CC];
__device__ float g_hnew[NP*CC];
__device__ float g_h2  [NP*CC];
__device__ float g_t512[NP*FF];
__device__ int   g_idx [NP*KK];
__device__ __nv_bfloat16 g_Dh[(size_t)NR*256];   // GEMM output, bf16: [d-part | l-part]

__device__ float    g_WinT[CIN*CC];
__device__ float    g_WvT [CC*CC];
__device__ float    g_WaqT[CC*CC];
__device__ float    g_WakT[CC*CC];
__device__ float    g_cd  [CC];              // Wa@bd2 + ba
// B operand, repacked for LDG.128:
// g_W2p[col*128 + (k&3)*32 + (k>>2)] = tf32(W[k][col]), col 0..127 = Wd2T, 128..255 = (WaWd2)T
__device__ unsigned g_W2p [256*CC];
__device__ float    g_Wf1T[CC*FF];
__device__ float    g_Wf2T[FF*CC];

// ---------------- helpers ----------------------------------------------------
__device__ __forceinline__ unsigned long long pack2(float x){
    unsigned long long r; asm("mov.b64 %0, {%1, %1};" : "=l"(r) : "f"(x)); return r;
}
__device__ __forceinline__ void fma2(unsigned long long &a, unsigned long long b, unsigned long long c){
    asm("fma.rn.f32x2 %0, %1, %2, %0;" : "+l"(a) : "l"(b), "l"(c));
}
__device__ __forceinline__ float2 unpack2(unsigned long long v){
    float2 f; asm("mov.b64 {%0, %1}, %2;" : "=f"(f.x), "=f"(f.y) : "l"(v)); return f;
}
__device__ __forceinline__ unsigned f2tf32(float f){
    unsigned u; asm("cvt.rna.tf32.f32 %0, %1;" : "=r"(u) : "f"(f)); return u;
}
__device__ __forceinline__ void mma_tf32(float* d, const unsigned* a, const unsigned* b){
    asm("mma.sync.aligned.m16n8k8.row.col.f32.tf32.tf32.f32 "
        "{%0,%1,%2,%3},{%4,%5,%6,%7},{%8,%9},{%0,%1,%2,%3};"
        : "+f"(d[0]),"+f"(d[1]),"+f"(d[2]),"+f"(d[3])
        : "r"(a[0]),"r"(a[1]),"r"(a[2]),"r"(a[3]), "r"(b[0]),"r"(b[1]));
}

// ---------------- prep kernels -----------------------------------------------
__global__ void k_prep_tr(const float* __restrict__ Win, const float* __restrict__ Wd2,
                          const float* __restrict__ Wv,  const float* __restrict__ Wf1,
                          const float* __restrict__ Wf2){
    int i = blockIdx.x*blockDim.x + threadIdx.x;   // 0..65535
    if (i < CIN*CC){ int c=i>>7, o=i&127; g_WinT[i] = Win[o*CIN+c]; }
    if (i < CC*CC){  int c=i>>7, o=i&127;           // c = k index, o = col
        float wd2 = Wd2[o*CC+c];
        g_W2p[o*128 + (c&3)*32 + (c>>2)] = f2tf32(wd2);
        g_WvT[i] = Wv[o*CC+c]; }
    if (i < CC*FF){  int c=i>>9, r=i&511; g_Wf1T[i] = Wf1[r*CC+c]; }
    if (i < FF*CC){  int r=i>>7, o=i&127; g_Wf2T[i] = Wf2[o*FF+r]; }
}

__global__ void k_prep_combo(const float* __restrict__ Wa, const float* __restrict__ Wq,
                             const float* __restrict__ Wk, const float* __restrict__ Wd2){
    int o = blockIdx.x;          // 0..127 (output row of combo = B column)
    int c = threadIdx.x;         // 0..127 (k index)
    const float* src = (blockIdx.y==0)?Wq : (blockIdx.y==1)?Wk : Wd2;
    float acc = 0.f;
    #pragma unroll 4
    for (int m=0; m<CC; m++) acc = fmaf(Wa[o*CC+m], src[m*CC+c], acc);
    if (blockIdx.y==0)      g_WaqT[c*CC+o] = acc;
    else if (blockIdx.y==1) g_WakT[c*CC+o] = acc;
    else                    g_W2p[(128+o)*128 + (c&3)*32 + (c>>2)] = f2tf32(acc);
}

__global__ void k_prep_cd(const float* __restrict__ Wa, const float* __restrict__ bd2,
                          const float* __restrict__ ba){
    int o = threadIdx.x;
    float acc = ba[o];
    #pragma unroll 4
    for (int c=0;c<CC;c++) acc = fmaf(Wa[o*CC+c], bd2[c], acc);
    g_cd[o] = acc;
}

// ---------------- KNN: warp-per-query, register top-16 ------------------------
// Launched 4th so the harness ncu window (-s 5 -c 1) captures it.
__global__ void __launch_bounds__(512) k_knn(const float* __restrict__ p, int* __restrict__ idx_out){
    __shared__ float px[NN], py[NN], pz[NN], sw[NN];
    int blk = blockIdx.x;
    int b   = blk >> 7;
    int n0  = (blk & 127) << 4;
    int tid = threadIdx.x, lane = tid & 31, w = tid >> 5;
    const float* pb = p + (size_t)b*3*NN;
    for (int i=tid;i<NN;i+=512){
        float x=pb[i], y=pb[NN+i], z=pb[2*NN+i];
        px[i]=x; py[i]=y; pz[i]=z;
        sw[i]=x*x + y*y + z*z;
    }
    __syncthreads();
    int n = n0 + w;
    float qx=px[n], qy=py[n], qz=pz[n];
    float xxq = sw[n];
    float qx2 = 2.f*qx, qy2 = 2.f*qy, qz2 = 2.f*qz;
    unsigned long long t[16];
    #pragma unroll
    for (int a=0;a<16;a++) t[a]=0ull;
    #pragma unroll 4
    for (int i=lane;i<NN;i+=32){
        float s = fmaf(qx2, px[i], fmaf(qy2, py[i], fmaf(qz2, pz[i], -xxq - sw[i])));
        unsigned u = __float_as_uint(s);
        u ^= (u & 0x80000000u) ? 0xFFFFFFFFu : 0x80000000u;
        unsigned long long key = ((unsigned long long)u << 32) | (unsigned)(~i);
        if (i == n) key = 0ull;
        if (key > t[15]){
            unsigned long long cur = key;
            #pragma unroll
            for (int a=0;a<16;a++){
                unsigned long long old = t[a];
                bool gt = cur > old;
                t[a] = gt ? cur : old;
                cur  = gt ? old : cur;
            }
        }
    }
    unsigned long long head = t[0];
    unsigned myres = 0;
    #pragma unroll
    for (int r=0;r<16;r++){
        unsigned long long m = head;
        #pragma unroll
        for (int o=16;o;o>>=1){
            unsigned long long v = __shfl_xor_sync(0xffffffffu, m, o);
            if (v > m) m = v;
        }
        if (lane == r) myres = ~(unsigned)m;
        if (head == m){
            #pragma unroll
            for (int a=0;a<15;a++) t[a]=t[a+1];
            t[15]=0ull;
            head = t[0];
        }
    }
    if (lane < KK) idx_out[((size_t)b*NN + n)*KK + lane] = (int)myres;
}

// ---------------- in_proj ----------------------------------------------------
__global__ void __launch_bounds__(128) k_inproj(const float* __restrict__ x,
                                                const float* __restrict__ binv){
    __shared__ __align__(16) float xs[CIN][16];
    int blk = blockIdx.x;
    int b   = blk >> 7;
    int n0  = (blk & 127) << 4;
    int pt0 = b*NN + n0;
    int tid = threadIdx.x;
    const float* xb = x + (size_t)b*CIN*NN;
    for (int f=tid; f<CIN*16; f+=128){ int c=f>>4, m=f&15; xs[c][m] = xb[c*NN + n0 + m]; }
    __syncthreads();
    unsigned long long acc[8];
    #pragma unroll
    for (int i=0;i<8;i++) acc[i]=0ull;
    #pragma unroll 2
    for (int c=0;c<CIN;c++){
        unsigned long long w2 = pack2(g_WinT[c*CC + tid]);
        const ulonglong2* xp = (const ulonglong2*)xs[c];
        ulonglong2 v0=xp[0], v1=xp[1], v2=xp[2], v3=xp[3];
        fma2(acc[0],w2,v0.x); fma2(acc[1],w2,v0.y);
        fma2(acc[2],w2,v1.x); fma2(acc[3],w2,v1.y);
        fma2(acc[4],w2,v2.x); fma2(acc[5],w2,v2.y);
        fma2(acc[6],w2,v3.x); fma2(acc[7],w2,v3.y);
    }
    float bo = binv[tid];
    #pragma unroll
    for (int i=0;i<8;i++){
        float2 f = unpack2(acc[i]);
        g_h[(size_t)(pt0+2*i)*CC   + tid] = f.x + bo;
        g_h[(size_t)(pt0+2*i+1)*CC + tid] = f.y + bo;
    }
}

// ---------------- LayerNorm ---------------------------------------------------
__global__ void __launch_bounds__(128) k_ln(const float* __restrict__ in, float* __restrict__ out,
                                            const float* __restrict__ g, const float* __restrict__ bbv){
    __shared__ float ws[4];
    int pt = blockIdx.x, t = threadIdx.x;
    float v = in[(size_t)pt*CC + t];
    float s = v;
    #pragma unroll
    for (int o=16;o;o>>=1) s += __shfl_xor_sync(0xffffffffu, s, o);
    if ((t&31)==0) ws[t>>5] = s;
    __syncthreads();
    float mu = (ws[0]+ws[1]+ws[2]+ws[3]) * (1.f/CC);
    float dv = v - mu;
    __syncthreads();
    float q = dv*dv;
    #pragma unroll
    for (int o=16;o;o>>=1) q += __shfl_xor_sync(0xffffffffu, q, o);
    if ((t&31)==0) ws[t>>5] = q;
    __syncthreads();
    float var = (ws[0]+ws[1]+ws[2]+ws[3]) * (1.f/CC);
    out[(size_t)pt*CC + t] = dv * rsqrtf(var + 1e-5f) * g[t] + bbv[t];
}

// ---------------- projections -------------------------------------------------
__global__ void __launch_bounds__(128) k_proj(){
    __shared__ __align__(16) float hs[CC][16];
    int pt0 = blockIdx.x * 16;
    int tid = threadIdx.x;
    for (int f=tid; f<CC*16; f+=128) hs[f&127][f>>7] = g_hn[(size_t)pt0*CC + f];
    __syncthreads();
    unsigned long long aq[8], ak[8], av[8];
    #pragma unroll
    for (int i=0;i<8;i++){ aq[i]=0ull; ak[i]=0ull; av[i]=0ull; }
    for (int c=0;c<CC;c++){
        unsigned long long wq = pack2(g_WaqT[c*CC+tid]);
        unsigned long long wk = pack2(g_WakT[c*CC+tid]);
        unsigned long long wv = pack2(g_WvT [c*CC+tid]);
        const ulonglong2* hp = (const ulonglong2*)hs[c];
        ulonglong2 v0=hp[0], v1=hp[1], v2=hp[2], v3=hp[3];
        fma2(aq[0],wq,v0.x); fma2(aq[1],wq,v0.y); fma2(aq[2],wq,v1.x); fma2(aq[3],wq,v1.y);
        fma2(aq[4],wq,v2.x); fma2(aq[5],wq,v2.y); fma2(aq[6],wq,v3.x); fma2(aq[7],wq,v3.y);
        fma2(ak[0],wk,v0.x); fma2(ak[1],wk,v0.y); fma2(ak[2],wk,v1.x); fma2(ak[3],wk,v1.y);
        fma2(ak[4],wk,v2.x); fma2(ak[5],wk,v2.y); fma2(ak[6],wk,v3.x); fma2(ak[7],wk,v3.y);
        fma2(av[0],wv,v0.x); fma2(av[1],wv,v0.y); fma2(av[2],wv,v1.x); fma2(av[3],wv,v1.y);
        fma2(av[4],wv,v2.x); fma2(av[5],wv,v2.y); fma2(av[6],wv,v3.x); fma2(av[7],wv,v3.y);
    }
    #pragma unroll
    for (int i=0;i<8;i++){
        float2 fq = unpack2(aq[i]), fk = unpack2(ak[i]), fv = unpack2(av[i]);
        size_t b0 = (size_t)(pt0+2*i)*CC + tid;
        size_t b1 = (size_t)(pt0+2*i+1)*CC + tid;
        g_qa[b0]=fq.x; g_qa[b1]=fq.y;
        g_ka[b0]=fk.x; g_ka[b1]=fk.y;
        g_v [b0]=fv.x; g_v [b1]=fv.y;
    }
}

// ---------------- attention GEMM: Dh[NR x 256] = relu(rel@Wd1^T+bd1) @ W2 ----
// tf32 mma.sync, block tile 128x128 (ntile 0..1), warp tile 64x32 (2x4 warps).
// B fetched via repacked LDG.128 (g_W2p); output stored bf16.
__global__ void __launch_bounds__(256) k_attn_gemm(const float* __restrict__ p,
                                                   const float* __restrict__ Wd1,
                                                   const float* __restrict__ bd1){
    extern __shared__ unsigned As[];          // [128][132] tf32 bits
    __shared__ float wd1s[CC][3];
    __shared__ float bd1s[CC];
    __shared__ float rel3[128][3];
    int tid  = threadIdx.x;
    int mtile = blockIdx.x;                   // 0..2047  (8 points each)
    int ntile = blockIdx.y;                   // 0..1
    int pt0 = mtile*8;

    if (tid < CC){
        wd1s[tid][0]=Wd1[tid*3]; wd1s[tid][1]=Wd1[tid*3+1]; wd1s[tid][2]=Wd1[tid*3+2];
        bd1s[tid]=bd1[tid];
    }
    if (tid < 128){
        int row = tid;
        int pt  = pt0 + (row>>4);
        int j   = row & 15;
        int b   = pt >> 11, n = pt & (NN-1);
        int jn  = g_idx[(size_t)pt*KK + j];
        const float* pb = p + (size_t)b*3*NN;
        rel3[row][0] = pb[n]      - pb[jn];
        rel3[row][1] = pb[NN+n]   - pb[NN+jn];
        rel3[row][2] = pb[2*NN+n] - pb[2*NN+jn];
    }
    __syncthreads();
    for (int e=tid; e<128*128; e+=256){
        int row = e >> 7, c = e & 127;
        float t = fmaf(wd1s[c][0], rel3[row][0],
                  fmaf(wd1s[c][1], rel3[row][1],
                  fmaf(wd1s[c][2], rel3[row][2], bd1s[c])));
        As[row*132 + c] = f2tf32(fmaxf(t, 0.f));
    }
    __syncthreads();

    int wid = tid >> 5, lane = tid & 31;
    int wm = wid & 1, wn = wid >> 1;          // 2 x 4 warp grid
    int g  = lane >> 2, tg = lane & 3;
    float acc[4][4][4];
    #pragma unroll
    for (int mi=0;mi<4;mi++)
        #pragma unroll
        for (int ni=0;ni<4;ni++)
            #pragma unroll
            for (int q=0;q<4;q++) acc[mi][ni][q]=0.f;

    int cg = ntile*128 + wn*32 + g;           // this thread's B column (+ni*8)
    const uint4* Bp = (const uint4*)(g_W2p + (size_t)cg*128 + tg*32);
    #pragma unroll
    for (int ks2=0; ks2<8; ks2++){
        uint4 bfr[4];
        #pragma unroll
        for (int ni=0;ni<4;ni++) bfr[ni] = Bp[ni*256 + ks2];   // ni*8 cols * 32 uint4/col
        #pragma unroll
        for (int ksi=0; ksi<2; ksi++){
            int k = (ks2*2 + ksi)*8;
            unsigned afr[4][4];
            #pragma unroll
            for (int mi=0;mi<4;mi++){
                int rb = wm*64 + mi*16;
                afr[mi][0] = As[(rb+g   )*132 + k + tg  ];
                afr[mi][1] = As[(rb+g+8 )*132 + k + tg  ];
                afr[mi][2] = As[(rb+g   )*132 + k + tg+4];
                afr[mi][3] = As[(rb+g+8 )*132 + k + tg+4];
            }
            #pragma unroll
            for (int ni=0;ni<4;ni++){
                unsigned bb[2];
                bb[0] = ksi ? bfr[ni].z : bfr[ni].x;
                bb[1] = ksi ? bfr[ni].w : bfr[ni].y;
                #pragma unroll
                for (int mi=0;mi<4;mi++) mma_tf32(acc[mi][ni], afr[mi], bb);
            }
        }
    }
    // epilogue: bf16 store
    #pragma unroll
    for (int mi=0;mi<4;mi++){
        int r0 = mtile*128 + wm*64 + mi*16 + g;
        #pragma unroll
        for (int ni=0;ni<4;ni++){
            int c0 = ntile*128 + wn*32 + ni*8 + 2*tg;
            *reinterpret_cast<__nv_bfloat162*>(&g_Dh[(size_t)r0*256 + c0]) =
                __float22bfloat162_rn(make_float2(acc[mi][ni][0], acc[mi][ni][1]));
            *reinterpret_cast<__nv_bfloat162*>(&g_Dh[(size_t)(r0+8)*256 + c0]) =
                __float22bfloat162_rn(make_float2(acc[mi][ni][2], acc[mi][ni][3]));
        }
    }
}

// ---------------- attention finish: softmax + combine ------------------------
__global__ void __launch_bounds__(128) k_finish(const float* __restrict__ bd2v){
    __shared__ int idxs[KK];
    int pt = blockIdx.x;
    int b  = pt >> 11;
    int tid = threadIdx.x;
    if (tid < KK) idxs[tid] = g_idx[(size_t)pt*KK + tid];
    __syncthreads();
    float bd2o = bd2v[tid];
    float base = g_qa[(size_t)pt*CC + tid] + g_cd[tid];
    float d[KK], l[KK];
    float mx = -3.4e38f;
    #pragma unroll
    for (int j=0;j<KK;j++){
        size_t r = (size_t)pt*KK + j;
        d[j] = __bfloat162float(g_Dh[r*256 + tid]) + bd2o;
        l[j] = __bfloat162float(g_Dh[r*256 + 128 + tid]) + base
             - g_ka[((size_t)b*NN + idxs[j])*CC + tid];
        mx = fmaxf(mx, l[j]);
    }
    float s = 0.f;
    #pragma unroll
    for (int j=0;j<KK;j++){ l[j] = __expf(l[j]-mx); s += l[j]; }
    float y = 0.f;
    #pragma unroll
    for (int j=0;j<KK;j++){
        float vj = g_v[((size_t)b*NN + idxs[j])*CC + tid];
        y = fmaf(l[j], vj + d[j], y);
    }
    y /= s;
    g_hnew[(size_t)pt*CC + tid] = g_h[(size_t)pt*CC + tid] + y;
}

// ---------------- FFN stage 1 -------------------------------------------------
__global__ void __launch_bounds__(256) k_ffn1(const float* __restrict__ bf1){
    __shared__ __align__(16) float hs[CC][16];
    int pt0 = blockIdx.x * 16;
    int tid = threadIdx.x;
    for (int f=tid; f<CC*16; f+=256) hs[f&127][f>>7] = g_h2[(size_t)pt0*CC + f];
    __syncthreads();
    unsigned long long a0[8], a1[8];
    #pragma unroll
    for (int i=0;i<8;i++){ a0[i]=0ull; a1[i]=0ull; }
    for (int c=0;c<CC;c++){
        unsigned long long w0 = pack2(g_Wf1T[c*FF + tid]);
        unsigned long long w1 = pack2(g_Wf1T[c*FF + tid + 256]);
        const ulonglong2* hp = (const ulonglong2*)hs[c];
        ulonglong2 v0=hp[0], v1=hp[1], v2=hp[2], v3=hp[3];
        fma2(a0[0],w0,v0.x); fma2(a0[1],w0,v0.y); fma2(a0[2],w0,v1.x); fma2(a0[3],w0,v1.y);
        fma2(a0[4],w0,v2.x); fma2(a0[5],w0,v2.y); fma2(a0[6],w0,v3.x); fma2(a0[7],w0,v3.y);
        fma2(a1[0],w1,v0.x); fma2(a1[1],w1,v0.y); fma2(a1[2],w1,v1.x); fma2(a1[3],w1,v1.y);
        fma2(a1[4],w1,v2.x); fma2(a1[5],w1,v2.y); fma2(a1[6],w1,v3.x); fma2(a1[7],w1,v3.y);
    }
    float b0 = bf1[tid], b1v = bf1[tid+256];
    #pragma unroll
    for (int i=0;i<8;i++){
        float2 f0 = unpack2(a0[i]), f1 = unpack2(a1[i]);
        g_t512[(size_t)(pt0+2*i)*FF   + tid]       = fmaxf(f0.x+b0, 0.f);
        g_t512[(size_t)(pt0+2*i+1)*FF + tid]       = fmaxf(f0.y+b0, 0.f);
        g_t512[(size_t)(pt0+2*i)*FF   + tid + 256] = fmaxf(f1.x+b1v, 0.f);
        g_t512[(size_t)(pt0+2*i+1)*FF + tid + 256] = fmaxf(f1.y+b1v, 0.f);
    }
}

// ---------------- FFN stage 2 + residual + transpose --------------------------
__global__ void __launch_bounds__(128) k_ffn2(const float* __restrict__ bf2, float* __restrict__ out){
    __shared__ __align__(16) float ts[FF][16];
    int pt0 = blockIdx.x * 16;
    int b   = pt0 >> 11;
    int n0  = pt0 & (NN-1);
    int tid = threadIdx.x;
    for (int f=tid; f<FF*16; f+=128) ts[f&511][f>>9] = g_t512[(size_t)pt0*FF + f];
    __syncthreads();
    unsigned long long acc[8];
    #pragma unroll
    for (int i=0;i<8;i++) acc[i]=0ull;
    #pragma unroll 2
    for (int r=0;r<FF;r++){
        unsigned long long w2 = pack2(g_Wf2T[r*CC + tid]);
        const ulonglong2* tp = (const ulonglong2*)ts[r];
        ulonglong2 v0=tp[0], v1=tp[1], v2=tp[2], v3=tp[3];
        fma2(acc[0],w2,v0.x); fma2(acc[1],w2,v0.y);
        fma2(acc[2],w2,v1.x); fma2(acc[3],w2,v1.y);
        fma2(acc[4],w2,v2.x); fma2(acc[5],w2,v2.y);
        fma2(acc[6],w2,v3.x); fma2(acc[7],w2,v3.y);
    }
    float bo = bf2[tid];
    float res[16];
    #pragma unroll
    for (int i=0;i<8;i++){
        float2 f = unpack2(acc[i]);
        res[2*i]   = g_hnew[(size_t)(pt0+2*i)*CC   + tid] + f.x + bo;
        res[2*i+1] = g_hnew[(size_t)(pt0+2*i+1)*CC + tid] + f.y + bo;
    }
    __syncthreads();
    float* os = &ts[0][0];
    #pragma unroll
    for (int m=0;m<16;m++) os[m*CC + tid] = res[m];
    __syncthreads();
    for (int f=tid; f<16*CC; f+=128){
        int o = f >> 4, m = f & 15;
        out[(size_t)b*CC*NN + (size_t)o*NN + n0 + m] = os[m*CC + o];
    }
}

// ---------------- launch ------------------------------------------------------
extern "C" void kernel_launch(void* const* d_in, const int* in_sizes, int n_in,
                              void* d_out, int out_size){
    const float* x    = (const float*)d_in[0];
    const float* p    = (const float*)d_in[1];
    const float* Win  = (const float*)d_in[2];
    const float* bin_ = (const float*)d_in[3];
    const float* Wq   = (const float*)d_in[4];
    const float* Wk   = (const float*)d_in[5];
    const float* Wv   = (const float*)d_in[6];
    const float* Wd1  = (const float*)d_in[7];
    const float* bd1  = (const float*)d_in[8];
    const float* Wd2  = (const float*)d_in[9];
    const float* bd2  = (const float*)d_in[10];
    const float* Wa   = (const float*)d_in[11];
    const float* ba   = (const float*)d_in[12];
    const float* g1   = (const float*)d_in[13];
    const float* b1   = (const float*)d_in[14];
    const float* g2   = (const float*)d_in[15];
    const float* b2   = (const float*)d_in[16];
    const float* Wf1  = (const float*)d_in[17];
    const float* bf1  = (const float*)d_in[18];
    const float* Wf2  = (const float*)d_in[19];
    const float* bf2  = (const float*)d_in[20];
    float* out = (float*)d_out;

    const int GEMM_SMEM = 128*132*4;   // 67584
    cudaFuncSetAttribute(k_attn_gemm, cudaFuncAttributeMaxDynamicSharedMemorySize, GEMM_SMEM);

    // launches 1-3: prep
    k_prep_tr<<<256, 256>>>(Win, Wd2, Wv, Wf1, Wf2);
    k_prep_combo<<<dim3(128,3), 128>>>(Wa, Wq, Wk, Wd2);
    k_prep_cd<<<1, 128>>>(Wa, bd2, ba);

    // launch 4: knn (positioned here so ncu -s 5 -c 1 captures it)
    {
        int* ip; cudaGetSymbolAddress((void**)&ip, g_idx);
        k_knn<<<NP/16, 512>>>(p, ip);
    }

    k_inproj<<<NP/16, 128>>>(x, bin_);
    {
        float *hp, *hnp;
        cudaGetSymbolAddress((void**)&hp,  g_h);
        cudaGetSymbolAddress((void**)&hnp, g_hn);
        k_ln<<<NP, 128>>>(hp, hnp, g1, b1);
    }
    k_proj<<<NP/16, 128>>>();
    k_attn_gemm<<<dim3(NR/128, 2), 256, GEMM_SMEM>>>(p, Wd1, bd1);
    k_finish<<<NP, 128>>>(bd2);
    {
        float *hp, *h2p;
        cudaGetSymbolAddress((void**)&hp,  g_hnew);
        cudaGetSymbolAddress((void**)&h2p, g_h2);
        k_ln<<<NP, 128>>>(hp, h2p, g2, b2);
    }
    k_ffn1<<<NP/16, 256>>>(bf1);
    k_ffn2<<<NP/16, 128>>>(bf2, out);
}

// round 14
// speedup vs baseline: 1.3047x; 1.2609x over previous
#include <cuda_runtime.h>
#include <cuda_bf16.h>

// Problem constants
#define BB 8
#define NN 2048
#define CIN 64
#define CC 128
#define KK 16
#define FF 512
#define NP (BB*NN)          // 16384 points
#define NR (NP*KK)          // 262144 t-rows

// ---------------- scratch ----------------------------------------------------
__device__ float g_h   [NP*CC];
__device__ float g_hn  [NP*CC];
__device__ float g_qa  [NP*CC];
__device__ float g_ka  [NP*CC];
__device__ float g_v   [NP*CC];
__device__ float g_hnew[NP*CC];
__device__ float g_h2  [NP*CC];
__device__ float g_t512[NP*FF];
__device__ int   g_idx [NP*KK];
__device__ __nv_bfloat16 g_Dh[(size_t)NR*256];   // GEMM output, bf16: [d-part | l-part]

__device__ float    g_WinT[CIN*CC];
__device__ float    g_WvT [CC*CC];
__device__ float    g_WaqT[CC*CC];
__device__ float    g_WakT[CC*CC];
__device__ float    g_cd  [CC];              // Wa@bd2 + ba
// B operand, repacked for LDG.128:
// g_W2p[col*128 + (k&3)*32 + (k>>2)] = tf32(W[k][col]), col 0..127 = Wd2T, 128..255 = (WaWd2)T
__device__ unsigned g_W2p [256*CC];
__device__ float    g_Wf1T[CC*FF];
__device__ float    g_Wf2T[FF*CC];

// ---------------- helpers ----------------------------------------------------
__device__ __forceinline__ unsigned long long pack2(float x){
    unsigned long long r; asm("mov.b64 %0, {%1, %1};" : "=l"(r) : "f"(x)); return r;
}
__device__ __forceinline__ void fma2(unsigned long long &a, unsigned long long b, unsigned long long c){
    asm("fma.rn.f32x2 %0, %1, %2, %0;" : "+l"(a) : "l"(b), "l"(c));
}
__device__ __forceinline__ float2 unpack2(unsigned long long v){
    float2 f; asm("mov.b64 {%0, %1}, %2;" : "=f"(f.x), "=f"(f.y) : "l"(v)); return f;
}
__device__ __forceinline__ unsigned f2tf32(float f){
    unsigned u; asm("cvt.rna.tf32.f32 %0, %1;" : "=r"(u) : "f"(f)); return u;
}
__device__ __forceinline__ void mma_tf32(float* d, const unsigned* a, const unsigned* b){
    asm("mma.sync.aligned.m16n8k8.row.col.f32.tf32.tf32.f32 "
        "{%0,%1,%2,%3},{%4,%5,%6,%7},{%8,%9},{%0,%1,%2,%3};"
        : "+f"(d[0]),"+f"(d[1]),"+f"(d[2]),"+f"(d[3])
        : "r"(a[0]),"r"(a[1]),"r"(a[2]),"r"(a[3]), "r"(b[0]),"r"(b[1]));
}

// ---------------- prep kernels -----------------------------------------------
__global__ void k_prep_tr(const float* __restrict__ Win, const float* __restrict__ Wd2,
                          const float* __restrict__ Wv,  const float* __restrict__ Wf1,
                          const float* __restrict__ Wf2){
    int i = blockIdx.x*blockDim.x + threadIdx.x;   // 0..65535
    if (i < CIN*CC){ int c=i>>7, o=i&127; g_WinT[i] = Win[o*CIN+c]; }
    if (i < CC*CC){  int c=i>>7, o=i&127;           // c = k index, o = col
        float wd2 = Wd2[o*CC+c];
        g_W2p[o*128 + (c&3)*32 + (c>>2)] = f2tf32(wd2);
        g_WvT[i] = Wv[o*CC+c]; }
    if (i < CC*FF){  int c=i>>9, r=i&511; g_Wf1T[i] = Wf1[r*CC+c]; }
    if (i < FF*CC){  int r=i>>7, o=i&127; g_Wf2T[i] = Wf2[o*FF+r]; }
}

__global__ void k_prep_combo(const float* __restrict__ Wa, const float* __restrict__ Wq,
                             const float* __restrict__ Wk, const float* __restrict__ Wd2){
    int o = blockIdx.x;          // 0..127 (output row of combo = B column)
    int c = threadIdx.x;         // 0..127 (k index)
    const float* src = (blockIdx.y==0)?Wq : (blockIdx.y==1)?Wk : Wd2;
    float acc = 0.f;
    #pragma unroll 4
    for (int m=0; m<CC; m++) acc = fmaf(Wa[o*CC+m], src[m*CC+c], acc);
    if (blockIdx.y==0)      g_WaqT[c*CC+o] = acc;
    else if (blockIdx.y==1) g_WakT[c*CC+o] = acc;
    else                    g_W2p[(128+o)*128 + (c&3)*32 + (c>>2)] = f2tf32(acc);
}

__global__ void k_prep_cd(const float* __restrict__ Wa, const float* __restrict__ bd2,
                          const float* __restrict__ ba){
    int o = threadIdx.x;
    float acc = ba[o];
    #pragma unroll 4
    for (int c=0;c<CC;c++) acc = fmaf(Wa[o*CC+c], bd2[c], acc);
    g_cd[o] = acc;
}

// ---------------- KNN: warp-distributed sorted top-16 ------------------------
// One warp per query. The top-16 list lives across lanes 0..15 (one (score,idx)
// per lane, sorted descending). Guard threshold = lane-15 score (global 16th).
// Insertion = O(1) warp-ops via shfl.up shift. No merge phase.
__global__ void __launch_bounds__(512) k_knn(const float* __restrict__ p, int* __restrict__ idx_out){
    __shared__ __align__(16) float4 pts[NN];   // 32KB: x,y,z,||p||^2
    int blk = blockIdx.x;                 // 0..1023, 16 queries each
    int b   = blk >> 7;
    int n0  = (blk & 127) << 4;
    int tid = threadIdx.x, lane = tid & 31, w = tid >> 5;
    const float* pb = p + (size_t)b*3*NN;
    for (int i=tid;i<NN;i+=512){
        float x=pb[i], y=pb[NN+i], z=pb[2*NN+i];
        pts[i] = make_float4(x, y, z, x*x + y*y + z*z);
    }
    __syncthreads();
    int n = n0 + w;
    float4 q = pts[n];
    float qx2 = 2.f*q.x, qy2 = 2.f*q.y, qz2 = 2.f*q.z;
    float nxx = -q.w;

    float sc = -3.4e38f;     // rank-`lane` score (valid lanes 0..15)
    int   ix = 0;
    float thr = -3.4e38f;    // lane-15 score, broadcast

    for (int t=0; t<NN/32; t++){
        int i = t*32 + lane;
        float4 c = pts[i];
        // s = -||q-p_i||^2 = 2 q.p_i - ||q||^2 - ||p_i||^2   (same FP order as before)
        float s = fmaf(qx2, c.x, fmaf(qy2, c.y, fmaf(qz2, c.z, nxx - c.w)));
        if (i == n) s = -3.4e38f;            // exclude self
        unsigned ball = __ballot_sync(0xffffffffu, s > thr);
        while (ball){
            int src = __ffs(ball) - 1;
            ball &= ball - 1;
            float cs = __shfl_sync(0xffffffffu, s, src);
            if (cs > thr){                    // thr may have risen (uniform branch)
                int ci = t*32 + src;
                float up_sc = __shfl_up_sync(0xffffffffu, sc, 1);
                int   up_ix = __shfl_up_sync(0xffffffffu, ix, 1);
                bool lt    = (sc < cs);       // strict: equal scores keep earlier idx (stable)
                bool up_lt = (lane == 0) ? false : (up_sc < cs);
                if (lt){
                    if (up_lt){ sc = up_sc; ix = up_ix; }
                    else      { sc = cs;    ix = ci;    }
                }
                thr = __shfl_sync(0xffffffffu, sc, 15);
            }
        }
    }
    if (lane < KK) idx_out[((size_t)b*NN + n)*KK + lane] = ix;
}

// ---------------- in_proj ----------------------------------------------------
__global__ void __launch_bounds__(128) k_inproj(const float* __restrict__ x,
                                                const float* __restrict__ binv){
    __shared__ __align__(16) float xs[CIN][16];
    int blk = blockIdx.x;
    int b   = blk >> 7;
    int n0  = (blk & 127) << 4;
    int pt0 = b*NN + n0;
    int tid = threadIdx.x;
    const float* xb = x + (size_t)b*CIN*NN;
    for (int f=tid; f<CIN*16; f+=128){ int c=f>>4, m=f&15; xs[c][m] = xb[c*NN + n0 + m]; }
    __syncthreads();
    unsigned long long acc[8];
    #pragma unroll
    for (int i=0;i<8;i++) acc[i]=0ull;
    #pragma unroll 2
    for (int c=0;c<CIN;c++){
        unsigned long long w2 = pack2(g_WinT[c*CC + tid]);
        const ulonglong2* xp = (const ulonglong2*)xs[c];
        ulonglong2 v0=xp[0], v1=xp[1], v2=xp[2], v3=xp[3];
        fma2(acc[0],w2,v0.x); fma2(acc[1],w2,v0.y);
        fma2(acc[2],w2,v1.x); fma2(acc[3],w2,v1.y);
        fma2(acc[4],w2,v2.x); fma2(acc[5],w2,v2.y);
        fma2(acc[6],w2,v3.x); fma2(acc[7],w2,v3.y);
    }
    float bo = binv[tid];
    #pragma unroll
    for (int i=0;i<8;i++){
        float2 f = unpack2(acc[i]);
        g_h[(size_t)(pt0+2*i)*CC   + tid] = f.x + bo;
        g_h[(size_t)(pt0+2*i+1)*CC + tid] = f.y + bo;
    }
}

// ---------------- LayerNorm ---------------------------------------------------
__global__ void __launch_bounds__(128) k_ln(const float* __restrict__ in, float* __restrict__ out,
                                            const float* __restrict__ g, const float* __restrict__ bbv){
    __shared__ float ws[4];
    int pt = blockIdx.x, t = threadIdx.x;
    float v = in[(size_t)pt*CC + t];
    float s = v;
    #pragma unroll
    for (int o=16;o;o>>=1) s += __shfl_xor_sync(0xffffffffu, s, o);
    if ((t&31)==0) ws[t>>5] = s;
    __syncthreads();
    float mu = (ws[0]+ws[1]+ws[2]+ws[3]) * (1.f/CC);
    float dv = v - mu;
    __syncthreads();
    float q = dv*dv;
    #pragma unroll
    for (int o=16;o;o>>=1) q += __shfl_xor_sync(0xffffffffu, q, o);
    if ((t&31)==0) ws[t>>5] = q;
    __syncthreads();
    float var = (ws[0]+ws[1]+ws[2]+ws[3]) * (1.f/CC);
    out[(size_t)pt*CC + t] = dv * rsqrtf(var + 1e-5f) * g[t] + bbv[t];
}

// ---------------- projections -------------------------------------------------
__global__ void __launch_bounds__(128) k_proj(){
    __shared__ __align__(16) float hs[CC][16];
    int pt0 = blockIdx.x * 16;
    int tid = threadIdx.x;
    for (int f=tid; f<CC*16; f+=128) hs[f&127][f>>7] = g_hn[(size_t)pt0*CC + f];
    __syncthreads();
    unsigned long long aq[8], ak[8], av[8];
    #pragma unroll
    for (int i=0;i<8;i++){ aq[i]=0ull; ak[i]=0ull; av[i]=0ull; }
    for (int c=0;c<CC;c++){
        unsigned long long wq = pack2(g_WaqT[c*CC+tid]);
        unsigned long long wk = pack2(g_WakT[c*CC+tid]);
        unsigned long long wv = pack2(g_WvT [c*CC+tid]);
        const ulonglong2* hp = (const ulonglong2*)hs[c];
        ulonglong2 v0=hp[0], v1=hp[1], v2=hp[2], v3=hp[3];
        fma2(aq[0],wq,v0.x); fma2(aq[1],wq,v0.y); fma2(aq[2],wq,v1.x); fma2(aq[3],wq,v1.y);
        fma2(aq[4],wq,v2.x); fma2(aq[5],wq,v2.y); fma2(aq[6],wq,v3.x); fma2(aq[7],wq,v3.y);
        fma2(ak[0],wk,v0.x); fma2(ak[1],wk,v0.y); fma2(ak[2],wk,v1.x); fma2(ak[3],wk,v1.y);
        fma2(ak[4],wk,v2.x); fma2(ak[5],wk,v2.y); fma2(ak[6],wk,v3.x); fma2(ak[7],wk,v3.y);
        fma2(av[0],wv,v0.x); fma2(av[1],wv,v0.y); fma2(av[2],wv,v1.x); fma2(av[3],wv,v1.y);
        fma2(av[4],wv,v2.x); fma2(av[5],wv,v2.y); fma2(av[6],wv,v3.x); fma2(av[7],wv,v3.y);
    }
    #pragma unroll
    for (int i=0;i<8;i++){
        float2 fq = unpack2(aq[i]), fk = unpack2(ak[i]), fv = unpack2(av[i]);
        size_t b0 = (size_t)(pt0+2*i)*CC + tid;
        size_t b1 = (size_t)(pt0+2*i+1)*CC + tid;
        g_qa[b0]=fq.x; g_qa[b1]=fq.y;
        g_ka[b0]=fk.x; g_ka[b1]=fk.y;
        g_v [b0]=fv.x; g_v [b1]=fv.y;
    }
}

// ---------------- attention GEMM: Dh[NR x 256] = relu(rel@Wd1^T+bd1) @ W2 ----
// tf32 mma.sync, block tile 128x128 (ntile 0..1), warp tile 64x32 (2x4 warps).
// B fetched via repacked LDG.128 (g_W2p); output stored bf16.
__global__ void __launch_bounds__(256) k_attn_gemm(const float* __restrict__ p,
                                                   const float* __restrict__ Wd1,
                                                   const float* __restrict__ bd1){
    extern __shared__ unsigned As[];          // [128][132] tf32 bits
    __shared__ float wd1s[CC][3];
    __shared__ float bd1s[CC];
    __shared__ float rel3[128][3];
    int tid  = threadIdx.x;
    int mtile = blockIdx.x;                   // 0..2047  (8 points each)
    int ntile = blockIdx.y;                   // 0..1
    int pt0 = mtile*8;

    if (tid < CC){
        wd1s[tid][0]=Wd1[tid*3]; wd1s[tid][1]=Wd1[tid*3+1]; wd1s[tid][2]=Wd1[tid*3+2];
        bd1s[tid]=bd1[tid];
    }
    if (tid < 128){
        int row = tid;
        int pt  = pt0 + (row>>4);
        int j   = row & 15;
        int b   = pt >> 11, n = pt & (NN-1);
        int jn  = g_idx[(size_t)pt*KK + j];
        const float* pb = p + (size_t)b*3*NN;
        rel3[row][0] = pb[n]      - pb[jn];
        rel3[row][1] = pb[NN+n]   - pb[NN+jn];
        rel3[row][2] = pb[2*NN+n] - pb[2*NN+jn];
    }
    __syncthreads();
    for (int e=tid; e<128*128; e+=256){
        int row = e >> 7, c = e & 127;
        float t = fmaf(wd1s[c][0], rel3[row][0],
                  fmaf(wd1s[c][1], rel3[row][1],
                  fmaf(wd1s[c][2], rel3[row][2], bd1s[c])));
        As[row*132 + c] = f2tf32(fmaxf(t, 0.f));
    }
    __syncthreads();

    int wid = tid >> 5, lane = tid & 31;
    int wm = wid & 1, wn = wid >> 1;          // 2 x 4 warp grid
    int g  = lane >> 2, tg = lane & 3;
    float acc[4][4][4];
    #pragma unroll
    for (int mi=0;mi<4;mi++)
        #pragma unroll
        for (int ni=0;ni<4;ni++)
            #pragma unroll
            for (int q=0;q<4;q++) acc[mi][ni][q]=0.f;

    int cg = ntile*128 + wn*32 + g;           // this thread's B column (+ni*8)
    const uint4* Bp = (const uint4*)(g_W2p + (size_t)cg*128 + tg*32);
    #pragma unroll
    for (int ks2=0; ks2<8; ks2++){
        uint4 bfr[4];
        #pragma unroll
        for (int ni=0;ni<4;ni++) bfr[ni] = Bp[ni*256 + ks2];   // ni*8 cols * 32 uint4/col
        #pragma unroll
        for (int ksi=0; ksi<2; ksi++){
            int k = (ks2*2 + ksi)*8;
            unsigned afr[4][4];
            #pragma unroll
            for (int mi=0;mi<4;mi++){
                int rb = wm*64 + mi*16;
                afr[mi][0] = As[(rb+g   )*132 + k + tg  ];
                afr[mi][1] = As[(rb+g+8 )*132 + k + tg  ];
                afr[mi][2] = As[(rb+g   )*132 + k + tg+4];
                afr[mi][3] = As[(rb+g+8 )*132 + k + tg+4];
            }
            #pragma unroll
            for (int ni=0;ni<4;ni++){
                unsigned bb[2];
                bb[0] = ksi ? bfr[ni].z : bfr[ni].x;
                bb[1] = ksi ? bfr[ni].w : bfr[ni].y;
                #pragma unroll
                for (int mi=0;mi<4;mi++) mma_tf32(acc[mi][ni], afr[mi], bb);
            }
        }
    }
    // epilogue: bf16 store
    #pragma unroll
    for (int mi=0;mi<4;mi++){
        int r0 = mtile*128 + wm*64 + mi*16 + g;
        #pragma unroll
        for (int ni=0;ni<4;ni++){
            int c0 = ntile*128 + wn*32 + ni*8 + 2*tg;
            *reinterpret_cast<__nv_bfloat162*>(&g_Dh[(size_t)r0*256 + c0]) =
                __float22bfloat162_rn(make_float2(acc[mi][ni][0], acc[mi][ni][1]));
            *reinterpret_cast<__nv_bfloat162*>(&g_Dh[(size_t)(r0+8)*256 + c0]) =
                __float22bfloat162_rn(make_float2(acc[mi][ni][2], acc[mi][ni][3]));
        }
    }
}

// ---------------- attention finish: softmax + combine ------------------------
__global__ void __launch_bounds__(128) k_finish(const float* __restrict__ bd2v){
    __shared__ int idxs[KK];
    int pt = blockIdx.x;
    int b  = pt >> 11;
    int tid = threadIdx.x;
    if (tid < KK) idxs[tid] = g_idx[(size_t)pt*KK + tid];
    __syncthreads();
    float bd2o = bd2v[tid];
    float base = g_qa[(size_t)pt*CC + tid] + g_cd[tid];
    float d[KK], l[KK];
    float mx = -3.4e38f;
    #pragma unroll
    for (int j=0;j<KK;j++){
        size_t r = (size_t)pt*KK + j;
        d[j] = __bfloat162float(g_Dh[r*256 + tid]) + bd2o;
        l[j] = __bfloat162float(g_Dh[r*256 + 128 + tid]) + base
             - g_ka[((size_t)b*NN + idxs[j])*CC + tid];
        mx = fmaxf(mx, l[j]);
    }
    float s = 0.f;
    #pragma unroll
    for (int j=0;j<KK;j++){ l[j] = __expf(l[j]-mx); s += l[j]; }
    float y = 0.f;
    #pragma unroll
    for (int j=0;j<KK;j++){
        float vj = g_v[((size_t)b*NN + idxs[j])*CC + tid];
        y = fmaf(l[j], vj + d[j], y);
    }
    y /= s;
    g_hnew[(size_t)pt*CC + tid] = g_h[(size_t)pt*CC + tid] + y;
}

// ---------------- FFN stage 1 -------------------------------------------------
__global__ void __launch_bounds__(256) k_ffn1(const float* __restrict__ bf1){
    __shared__ __align__(16) float hs[CC][16];
    int pt0 = blockIdx.x * 16;
    int tid = threadIdx.x;
    for (int f=tid; f<CC*16; f+=256) hs[f&127][f>>7] = g_h2[(size_t)pt0*CC + f];
    __syncthreads();
    unsigned long long a0[8], a1[8];
    #pragma unroll
    for (int i=0;i<8;i++){ a0[i]=0ull; a1[i]=0ull; }
    for (int c=0;c<CC;c++){
        unsigned long long w0 = pack2(g_Wf1T[c*FF + tid]);
        unsigned long long w1 = pack2(g_Wf1T[c*FF + tid + 256]);
        const ulonglong2* hp = (const ulonglong2*)hs[c];
        ulonglong2 v0=hp[0], v1=hp[1], v2=hp[2], v3=hp[3];
        fma2(a0[0],w0,v0.x); fma2(a0[1],w0,v0.y); fma2(a0[2],w0,v1.x); fma2(a0[3],w0,v1.y);
        fma2(a0[4],w0,v2.x); fma2(a0[5],w0,v2.y); fma2(a0[6],w0,v3.x); fma2(a0[7],w0,v3.y);
        fma2(a1[0],w1,v0.x); fma2(a1[1],w1,v0.y); fma2(a1[2],w1,v1.x); fma2(a1[3],w1,v1.y);
        fma2(a1[4],w1,v2.x); fma2(a1[5],w1,v2.y); fma2(a1[6],w1,v3.x); fma2(a1[7],w1,v3.y);
    }
    float b0 = bf1[tid], b1v = bf1[tid+256];
    #pragma unroll
    for (int i=0;i<8;i++){
        float2 f0 = unpack2(a0[i]), f1 = unpack2(a1[i]);
        g_t512[(size_t)(pt0+2*i)*FF   + tid]       = fmaxf(f0.x+b0, 0.f);
        g_t512[(size_t)(pt0+2*i+1)*FF + tid]       = fmaxf(f0.y+b0, 0.f);
        g_t512[(size_t)(pt0+2*i)*FF   + tid + 256] = fmaxf(f1.x+b1v, 0.f);
        g_t512[(size_t)(pt0+2*i+1)*FF + tid + 256] = fmaxf(f1.y+b1v, 0.f);
    }
}

// ---------------- FFN stage 2 + residual + transpose --------------------------
__global__ void __launch_bounds__(128) k_ffn2(const float* __restrict__ bf2, float* __restrict__ out){
    __shared__ __align__(16) float ts[FF][16];
    int pt0 = blockIdx.x * 16;
    int b   = pt0 >> 11;
    int n0  = pt0 & (NN-1);
    int tid = threadIdx.x;
    for (int f=tid; f<FF*16; f+=128) ts[f&511][f>>9] = g_t512[(size_t)pt0*FF + f];
    __syncthreads();
    unsigned long long acc[8];
    #pragma unroll
    for (int i=0;i<8;i++) acc[i]=0ull;
    #pragma unroll 2
    for (int r=0;r<FF;r++){
        unsigned long long w2 = pack2(g_Wf2T[r*CC + tid]);
        const ulonglong2* tp = (const ulonglong2*)ts[r];
        ulonglong2 v0=tp[0], v1=tp[1], v2=tp[2], v3=tp[3];
        fma2(acc[0],w2,v0.x); fma2(acc[1],w2,v0.y);
        fma2(acc[2],w2,v1.x); fma2(acc[3],w2,v1.y);
        fma2(acc[4],w2,v2.x); fma2(acc[5],w2,v2.y);
        fma2(acc[6],w2,v3.x); fma2(acc[7],w2,v3.y);
    }
    float bo = bf2[tid];
    float res[16];
    #pragma unroll
    for (int i=0;i<8;i++){
        float2 f = unpack2(acc[i]);
        res[2*i]   = g_hnew[(size_t)(pt0+2*i)*CC   + tid] + f.x + bo;
        res[2*i+1] = g_hnew[(size_t)(pt0+2*i+1)*CC + tid] + f.y + bo;
    }
    __syncthreads();
    float* os = &ts[0][0];
    #pragma unroll
    for (int m=0;m<16;m++) os[m*CC + tid] = res[m];
    __syncthreads();
    for (int f=tid; f<16*CC; f+=128){
        int o = f >> 4, m = f & 15;
        out[(size_t)b*CC*NN + (size_t)o*NN + n0 + m] = os[m*CC + o];
    }
}

// ---------------- launch ------------------------------------------------------
extern "C" void kernel_launch(void* const* d_in, const int* in_sizes, int n_in,
                              void* d_out, int out_size){
    const float* x    = (const float*)d_in[0];
    const float* p    = (const float*)d_in[1];
    const float* Win  = (const float*)d_in[2];
    const float* bin_ = (const float*)d_in[3];
    const float* Wq   = (const float*)d_in[4];
    const float* Wk   = (const float*)d_in[5];
    const float* Wv   = (const float*)d_in[6];
    const float* Wd1  = (const float*)d_in[7];
    const float* bd1  = (const float*)d_in[8];
    const float* Wd2  = (const float*)d_in[9];
    const float* bd2  = (const float*)d_in[10];
    const float* Wa   = (const float*)d_in[11];
    const float* ba   = (const float*)d_in[12];
    const float* g1   = (const float*)d_in[13];
    const float* b1   = (const float*)d_in[14];
    const float* g2   = (const float*)d_in[15];
    const float* b2   = (const float*)d_in[16];
    const float* Wf1  = (const float*)d_in[17];
    const float* bf1  = (const float*)d_in[18];
    const float* Wf2  = (const float*)d_in[19];
    const float* bf2  = (const float*)d_in[20];
    float* out = (float*)d_out;

    const int GEMM_SMEM = 128*132*4;   // 67584
    cudaFuncSetAttribute(k_attn_gemm, cudaFuncAttributeMaxDynamicSharedMemorySize, GEMM_SMEM);

    // launches 1-3: prep + knn (gemm deps only: W2p, idx)
    k_prep_tr<<<256, 256>>>(Win, Wd2, Wv, Wf1, Wf2);
    k_prep_combo<<<dim3(128,3), 128>>>(Wa, Wq, Wk, Wd2);
    {
        int* ip; cudaGetSymbolAddress((void**)&ip, g_idx);
        k_knn<<<NP/16, 512>>>(p, ip);
    }
    // launch 4: attention GEMM (positioned so ncu -s 5 -c 1 captures it)
    k_attn_gemm<<<dim3(NR/128, 2), 256, GEMM_SMEM>>>(p, Wd1, bd1);

    k_prep_cd<<<1, 128>>>(Wa, bd2, ba);
    k_inproj<<<NP/16, 128>>>(x, bin_);
    {
        float *hp, *hnp;
        cudaGetSymbolAddress((void**)&hp,  g_h);
        cudaGetSymbolAddress((void**)&hnp, g_hn);
        k_ln<<<NP, 128>>>(hp, hnp, g1, b1);
    }
    k_proj<<<NP/16, 128>>>();
    k_finish<<<NP, 128>>>(bd2);
    {
        float *hp, *h2p;
        cudaGetSymbolAddress((void**)&hp,  g_hnew);
        cudaGetSymbolAddress((void**)&h2p, g_h2);
        k_ln<<<NP, 128>>>(hp, h2p, g2, b2);
    }
    k_ffn1<<<NP/16, 256>>>(bf1);
    k_ffn2<<<NP/16, 128>>>(bf2, out);
}